// round 12
// baseline (speedup 1.0000x reference)
#include <cuda_runtime.h>
#include <math.h>

#define T    2048
#define F    1024
#define NB   64          // total batch
#define HB   32          // half batch
#define KSEL 20

// scratch (no allocs allowed)
__device__ float g_mags[NB * T];

// -------- kernel 1: per-(b,t) L2 norm over feature dim --------
// one warp per row; 8 float4 loads per lane, fully coalesced. HBM-bound
// at ~6.9 TB/s (86% of spec) — measured roofline. Untouched.
__global__ void mag_kernel(const float* __restrict__ feat) {
    int warp = (blockIdx.x * blockDim.x + threadIdx.x) >> 5;  // 0 .. 64*2048-1
    int lane = threadIdx.x & 31;
    const float4* row = (const float4*)(feat + (size_t)warp * F);
    float s = 0.f;
#pragma unroll
    for (int i = 0; i < 8; i++) {
        float4 v = row[lane + i * 32];
        s += v.x * v.x + v.y * v.y + v.z * v.z + v.w * v.w;
    }
#pragma unroll
    for (int o = 16; o; o >>= 1) s += __shfl_xor_sync(0xffffffffu, s, o);
    if (lane == 0) g_mags[warp] = sqrtf(s);
}

// -------- kernel 2: fused redundant-topk + gather (1280 blocks) ------------
// Each block recomputes its batch's FULL top-20 locally (no cross-block
// communication — redundancy is free, all blocks fit in one wave), then
// copies its single assigned feature row. k==0 blocks also write the score
// mean. Warp-local top-20 + single-warp 8-way merge; stable (value desc,
// index asc) tie-break matches jax.lax.top_k.
__global__ void __launch_bounds__(256)
topk_gather_kernel(const float* __restrict__ feat,
                   const float* __restrict__ scores,
                   const float* __restrict__ mask_abn,
                   const float* __restrict__ mask_nor,
                   float* __restrict__ out) {
    __shared__ float s_wv[8][21];
    __shared__ int   s_wi[8][21];
    __shared__ int   s_sel[KSEL];

    int r = blockIdx.x / KSEL;       // output row 0..63 (abn rows first)
    int k = blockIdx.x % KSEL;       // which of the 20 selected rows to copy
    int tid = threadIdx.x;
    int lane = tid & 31;
    int wid = tid >> 5;

    int batch;
    const float* mask;
    if (r < HB) { batch = HB + r; mask = mask_abn + (size_t)r * T; }
    else        { batch = r - HB; mask = mask_nor + (size_t)(r - HB) * T; }

    const float inv = 1.0f / 0.9f;   // 1/(1-P)
    float v[8];
#pragma unroll
    for (int j = 0; j < 8; j++) {
        int t = wid * 256 + j * 32 + lane;    // warp owns contiguous 256
        float d = (mask[t] > 0.1f) ? inv : 0.0f;
        v[j] = g_mags[batch * T + t] * d;     // L2-broadcast across 20 blocks
    }

    // 20 warp-local rounds, no block syncs
    for (int kk = 0; kk < KSEL; kk++) {
        float bv = -1.0f; int bi = 1 << 30;
#pragma unroll
        for (int j = 0; j < 8; j++) {
            if (v[j] > bv) { bv = v[j]; bi = wid * 256 + j * 32 + lane; }
        }
#pragma unroll
        for (int o = 16; o; o >>= 1) {
            float ov = __shfl_xor_sync(0xffffffffu, bv, o);
            int   oi = __shfl_xor_sync(0xffffffffu, bi, o);
            if (ov > bv || (ov == bv && oi < bi)) { bv = ov; bi = oi; }
        }
        if (lane == 0) { s_wv[wid][kk] = bv; s_wi[wid][kk] = bi; }
        int local = bi - wid * 256;           // remove winner from registers
        if ((local & 31) == lane) v[local >> 5] = -1.0f;
    }
    if (lane == 0) { s_wv[wid][20] = -2.0f; s_wi[wid][20] = 1 << 30; }
    __syncthreads();

    // warp 0: merge 8 descending lists of 20 (lanes 0..7 hold list heads)
    if (wid == 0) {
        int   p  = 0;
        float hv = (lane < 8) ? s_wv[lane][0] : -3.0f;
        int   hi = (lane < 8) ? s_wi[lane][0] : (1 << 30);
        int my_idx = 0;
        for (int kk = 0; kk < KSEL; kk++) {
            float fv = hv; int fi = hi;
#pragma unroll
            for (int o = 4; o; o >>= 1) {
                float ov = __shfl_xor_sync(0xffffffffu, fv, o);
                int   oi = __shfl_xor_sync(0xffffffffu, fi, o);
                if (ov > fv || (ov == fv && oi < fi)) { fv = ov; fi = oi; }
            }
            fi = __shfl_sync(0xffffffffu, fi, 0);       // broadcast winner
            if (lane == kk) my_idx = fi;
            if (lane < 8 && hi == fi) {                 // advance that list
                p++; hv = s_wv[lane][p]; hi = s_wi[lane][p];
            }
        }
        if (lane < KSEL) s_sel[lane] = my_idx;

        // score mean: only the k==0 block of each row writes it
        if (k == 0) {
            float sc = 0.f;
            if (lane < KSEL) sc = scores[(size_t)batch * T + my_idx];
#pragma unroll
            for (int o = 16; o; o >>= 1) sc += __shfl_xor_sync(0xffffffffu, sc, o);
            if (lane == 0) out[r] = sc / (float)KSEL;  // [0,32)=abn, [32,64)=nor
        }
    }
    __syncthreads();

    // copy the k-th selected feature row (4KB, one float4 per thread)
    int idx = s_sel[k];
    const float4* src = (const float4*)(feat + ((size_t)batch * T + idx) * F);
    float4* dst = (float4*)(out + 64 + ((size_t)r * KSEL + k) * F);
    dst[tid] = src[tid];
}

extern "C" void kernel_launch(void* const* d_in, const int* in_sizes, int n_in,
                              void* d_out, int out_size) {
    const float* feat   = (const float*)d_in[0];
    const float* scores = (const float*)d_in[1];
    const float* mabn   = (const float*)d_in[2];
    const float* mnor   = (const float*)d_in[3];
    float* out = (float*)d_out;

    mag_kernel<<<(NB * T) / 8, 256>>>(feat);
    topk_gather_kernel<<<NB * KSEL, 256>>>(feat, scores, mabn, mnor, out);
}

// round 13
// speedup vs baseline: 1.0914x; 1.0914x over previous
#include <cuda_runtime.h>
#include <math.h>

#define T    2048
#define F    1024
#define NB   64          // total batch
#define HB   32          // half batch
#define KSEL 20

// scratch (no allocs allowed)
__device__ float g_mags[NB * T];

// -------- kernel 1: per-(b,t) L2 norm over feature dim --------
// one warp per row; 8 float4 loads per lane, fully coalesced. HBM-bound
// at ~6.9 TB/s (86% of spec) — measured roofline. Untouched.
__global__ void mag_kernel(const float* __restrict__ feat) {
    int warp = (blockIdx.x * blockDim.x + threadIdx.x) >> 5;  // 0 .. 64*2048-1
    int lane = threadIdx.x & 31;
    const float4* row = (const float4*)(feat + (size_t)warp * F);
    float s = 0.f;
#pragma unroll
    for (int i = 0; i < 8; i++) {
        float4 v = row[lane + i * 32];
        s += v.x * v.x + v.y * v.y + v.z * v.z + v.w * v.w;
    }
#pragma unroll
    for (int o = 16; o; o >>= 1) s += __shfl_xor_sync(0xffffffffu, s, o);
    if (lane == 0) g_mags[warp] = sqrtf(s);
}

// -------- kernel 2: topk + score mean + gather, 64 blocks x 1024 threads --
// One block per output row; top-20 computed ONCE per block (R12's 20x
// redundancy was ALU-issue-bound), then the block gathers its own 20 rows
// with 5 independent float4 copies per thread. No cross-block communication.
__global__ void __launch_bounds__(1024)
topk_gather_kernel(const float* __restrict__ feat,
                   const float* __restrict__ scores,
                   const float* __restrict__ mask_abn,
                   const float* __restrict__ mask_nor,
                   float* __restrict__ out) {
    __shared__ float s_wv[32][21];
    __shared__ int   s_wi[32][21];
    __shared__ int   s_sel[KSEL];

    int r = blockIdx.x;              // output row 0..63 (abn rows first)
    int tid = threadIdx.x;
    int lane = tid & 31;
    int wid = tid >> 5;              // 0..31

    int batch;
    const float* mask;
    if (r < HB) { batch = HB + r; mask = mask_abn + (size_t)r * T; }
    else        { batch = r - HB; mask = mask_nor + (size_t)(r - HB) * T; }

    // each warp owns 64 contiguous candidates (2 regs/thread)
    const float inv = 1.0f / 0.9f;   // 1/(1-P)
    float v[2];
#pragma unroll
    for (int j = 0; j < 2; j++) {
        int t = wid * 64 + j * 32 + lane;
        float d = (mask[t] > 0.1f) ? inv : 0.0f;
        v[j] = g_mags[batch * T + t] * d;
    }

    // 20 warp-local rounds (2 reg cmps + 5-shfl tree each), no block syncs
    for (int k = 0; k < KSEL; k++) {
        float bv = -1.0f; int bi = 1 << 30;
#pragma unroll
        for (int j = 0; j < 2; j++) {
            if (v[j] > bv) { bv = v[j]; bi = wid * 64 + j * 32 + lane; }
        }
#pragma unroll
        for (int o = 16; o; o >>= 1) {
            float ov = __shfl_xor_sync(0xffffffffu, bv, o);
            int   oi = __shfl_xor_sync(0xffffffffu, bi, o);
            if (ov > bv || (ov == bv && oi < bi)) { bv = ov; bi = oi; }
        }
        if (lane == 0) { s_wv[wid][k] = bv; s_wi[wid][k] = bi; }
        int local = bi - wid * 64;            // remove winner from registers
        if ((local & 31) == lane) v[local >> 5] = -1.0f;
    }
    if (lane == 0) { s_wv[wid][20] = -2.0f; s_wi[wid][20] = 1 << 30; }
    __syncthreads();

    // warp 0: merge 32 descending lists of 20 (every lane holds a list head)
    if (wid == 0) {
        int   p  = 0;
        float hv = s_wv[lane][0];
        int   hi = s_wi[lane][0];
        int my_idx = 0;
        for (int k = 0; k < KSEL; k++) {
            float fv = hv; int fi = hi;
#pragma unroll
            for (int o = 16; o; o >>= 1) {
                float ov = __shfl_xor_sync(0xffffffffu, fv, o);
                int   oi = __shfl_xor_sync(0xffffffffu, fi, o);
                if (ov > fv || (ov == fv && oi < fi)) { fv = ov; fi = oi; }
            }
            fi = __shfl_sync(0xffffffffu, fi, 0);       // broadcast winner
            if (lane == k) my_idx = fi;
            if (hi == fi) {                             // advance that list
                p++; hv = s_wv[lane][p]; hi = s_wi[lane][p];
            }
        }
        if (lane < KSEL) s_sel[lane] = my_idx;

        // score mean
        float sc = 0.f;
        if (lane < KSEL) sc = scores[(size_t)batch * T + my_idx];
#pragma unroll
        for (int o = 16; o; o >>= 1) sc += __shfl_xor_sync(0xffffffffu, sc, o);
        if (lane == 0) out[r] = sc / (float)KSEL;   // [0,32)=abn, [32,64)=nor
    }
    __syncthreads();

    // gather: 20 rows x 256 float4 = 5120 float4; 1024 threads -> 5 each,
    // batched loads first (MLP=5), then stores
    const float4* srcp[5];
    int es[5];
#pragma unroll
    for (int i = 0; i < 5; i++) {
        int e = tid + i * 1024;          // 0..5119
        int k = e >> 8;                  // selected-row slot 0..19
        int c = e & 255;                 // float4 within row
        srcp[i] = (const float4*)(feat + ((size_t)batch * T + s_sel[k]) * F) + c;
        es[i] = e;
    }
    float4 buf[5];
#pragma unroll
    for (int i = 0; i < 5; i++) buf[i] = *srcp[i];
    float4* dst = (float4*)(out + 64 + (size_t)r * KSEL * F);
#pragma unroll
    for (int i = 0; i < 5; i++) dst[es[i]] = buf[i];
}

extern "C" void kernel_launch(void* const* d_in, const int* in_sizes, int n_in,
                              void* d_out, int out_size) {
    const float* feat   = (const float*)d_in[0];
    const float* scores = (const float*)d_in[1];
    const float* mabn   = (const float*)d_in[2];
    const float* mnor   = (const float*)d_in[3];
    float* out = (float*)d_out;

    mag_kernel<<<(NB * T) / 8, 256>>>(feat);
    topk_gather_kernel<<<NB, 1024>>>(feat, scores, mabn, mnor, out);
}

// round 14
// speedup vs baseline: 1.1927x; 1.0928x over previous
#include <cuda_runtime.h>
#include <math.h>

#define T    2048
#define F    1024
#define NB   64          // total batch
#define HB   32          // half batch
#define KSEL 20
#define GBLK 320         // gather blocks (all co-resident in one wave)
#define RPB  4           // rows copied per block (1280 / 320)

// scratch (no allocs allowed)
__device__ float g_mags[NB * T];
__device__ int   g_idx[NB * KSEL];
__device__ int   g_flag[NB];     // reset by mag_kernel each launch

__device__ __forceinline__ void st_release(int* p, int v) {
    asm volatile("st.release.gpu.global.b32 [%0], %1;" :: "l"(p), "r"(v) : "memory");
}
__device__ __forceinline__ int ld_acquire(const int* p) {
    int v;
    asm volatile("ld.acquire.gpu.global.b32 %0, [%1];" : "=r"(v) : "l"(p) : "memory");
    return v;
}

// -------- kernel 1: per-(b,t) L2 norm + flag reset ------------------------
// one warp per row; 8 float4 loads per lane. HBM-bound at 86% of spec —
// measured roofline, untouched. Also resets g_flag for the next graph node
// (kernel boundary provides the ordering).
__global__ void mag_kernel(const float* __restrict__ feat) {
    if (blockIdx.x < NB && threadIdx.x == 0) g_flag[blockIdx.x] = 0;

    int warp = (blockIdx.x * blockDim.x + threadIdx.x) >> 5;  // 0 .. 64*2048-1
    int lane = threadIdx.x & 31;
    const float4* row = (const float4*)(feat + (size_t)warp * F);
    float s = 0.f;
#pragma unroll
    for (int i = 0; i < 8; i++) {
        float4 v = row[lane + i * 32];
        s += v.x * v.x + v.y * v.y + v.z * v.z + v.w * v.w;
    }
#pragma unroll
    for (int o = 16; o; o >>= 1) s += __shfl_xor_sync(0xffffffffu, s, o);
    if (lane == 0) g_mags[warp] = sqrtf(s);
}

// -------- kernel 2: topk (blocks 0..63) + gather (all 320 blocks) ---------
// All 320 blocks are co-resident (first wave), so the flag spin is benign:
// it only overlaps the ~2.5us topk, not the 78us stream (the R6-R9 lesson).
__global__ void __launch_bounds__(256)
topk_gather_kernel(const float* __restrict__ feat,
                   const float* __restrict__ scores,
                   const float* __restrict__ mask_abn,
                   const float* __restrict__ mask_nor,
                   float* __restrict__ out) {
    int blk = blockIdx.x;
    int tid = threadIdx.x;
    int lane = tid & 31;
    int wid = tid >> 5;

    // ===== phase A: blocks 0..63 compute top-20 for output row r=blk ======
    if (blk < NB) {
        __shared__ float s_wv[8][21];
        __shared__ int   s_wi[8][21];

        int r = blk;
        int batch;
        const float* mask;
        if (r < HB) { batch = HB + r; mask = mask_abn + (size_t)r * T; }
        else        { batch = r - HB; mask = mask_nor + (size_t)(r - HB) * T; }

        const float inv = 1.0f / 0.9f;   // 1/(1-P)
        float v[8];
#pragma unroll
        for (int j = 0; j < 8; j++) {
            int t = wid * 256 + j * 32 + lane;    // warp owns contiguous 256
            float d = (mask[t] > 0.1f) ? inv : 0.0f;
            v[j] = g_mags[batch * T + t] * d;
        }

        // 20 warp-local rounds, no block syncs
        for (int k = 0; k < KSEL; k++) {
            float bv = -1.0f; int bi = 1 << 30;
#pragma unroll
            for (int j = 0; j < 8; j++) {
                if (v[j] > bv) { bv = v[j]; bi = wid * 256 + j * 32 + lane; }
            }
#pragma unroll
            for (int o = 16; o; o >>= 1) {
                float ov = __shfl_xor_sync(0xffffffffu, bv, o);
                int   oi = __shfl_xor_sync(0xffffffffu, bi, o);
                if (ov > bv || (ov == bv && oi < bi)) { bv = ov; bi = oi; }
            }
            if (lane == 0) { s_wv[wid][k] = bv; s_wi[wid][k] = bi; }
            int local = bi - wid * 256;           // remove winner
            if ((local & 31) == lane) v[local >> 5] = -1.0f;
        }
        if (lane == 0) { s_wv[wid][20] = -2.0f; s_wi[wid][20] = 1 << 30; }
        __syncthreads();

        // warp 0: merge 8 descending lists of 20; write idx, score mean, flag
        if (wid == 0) {
            int   p  = 0;
            float hv = (lane < 8) ? s_wv[lane][0] : -3.0f;
            int   hi = (lane < 8) ? s_wi[lane][0] : (1 << 30);
            int my_idx = 0;
            for (int k = 0; k < KSEL; k++) {
                float fv = hv; int fi = hi;
#pragma unroll
                for (int o = 4; o; o >>= 1) {
                    float ov = __shfl_xor_sync(0xffffffffu, fv, o);
                    int   oi = __shfl_xor_sync(0xffffffffu, fi, o);
                    if (ov > fv || (ov == fv && oi < fi)) { fv = ov; fi = oi; }
                }
                fi = __shfl_sync(0xffffffffu, fi, 0);    // broadcast winner
                if (lane == k) my_idx = fi;
                if (lane < 8 && hi == fi) {              // advance that list
                    p++; hv = s_wv[lane][p]; hi = s_wi[lane][p];
                }
            }
            float sc = 0.f;
            if (lane < KSEL) {
                g_idx[r * KSEL + lane] = my_idx;
                sc = scores[(size_t)batch * T + my_idx];
            }
#pragma unroll
            for (int o = 16; o; o >>= 1) sc += __shfl_xor_sync(0xffffffffu, sc, o);
            if (lane == 0) {
                out[r] = sc / (float)KSEL;   // [0,32)=abn, [32,64)=nor
                st_release(&g_flag[r], 1);   // release orders g_idx stores
            }
        }
        __syncthreads();
    }

    // ===== phase B: every block gathers RPB=4 rows ========================
    int e0 = blk * RPB;                  // first of my 4 row-units
    if (tid == 0) {
#pragma unroll
        for (int i = 0; i < RPB; i++) {
            int orow = (e0 + i) / KSEL;
            while (ld_acquire(&g_flag[orow]) == 0) __nanosleep(32);
        }
    }
    __syncthreads();

    const float4* srcp[RPB];
    int rows[RPB];
#pragma unroll
    for (int i = 0; i < RPB; i++) {
        int e    = e0 + i;               // row-unit 0..1279
        int orow = e / KSEL;             // output row 0..63 (abn first)
        int k    = e % KSEL;
        int batch = (orow < HB) ? (HB + orow) : (orow - HB);
        int idx = __ldcg(&g_idx[orow * KSEL + k]);   // bypass L1 (cross-SM)
        srcp[i] = (const float4*)(feat + ((size_t)batch * T + idx) * F) + tid;
        rows[i] = e;
    }
    float4 buf[RPB];
#pragma unroll
    for (int i = 0; i < RPB; i++) buf[i] = *srcp[i];   // batched: MLP=4
    float4* dst = (float4*)(out + 64);
#pragma unroll
    for (int i = 0; i < RPB; i++) dst[(size_t)rows[i] * 256 + tid] = buf[i];
}

extern "C" void kernel_launch(void* const* d_in, const int* in_sizes, int n_in,
                              void* d_out, int out_size) {
    const float* feat   = (const float*)d_in[0];
    const float* scores = (const float*)d_in[1];
    const float* mabn   = (const float*)d_in[2];
    const float* mnor   = (const float*)d_in[3];
    float* out = (float*)d_out;

    mag_kernel<<<(NB * T) / 8, 256>>>(feat);
    topk_gather_kernel<<<GBLK, 256>>>(feat, scores, mabn, mnor, out);
}

// round 15
// speedup vs baseline: 1.2705x; 1.0652x over previous
#include <cuda_runtime.h>
#include <math.h>

#define T    2048
#define F    1024
#define NB   64          // total batch
#define HB   32          // half batch
#define KSEL 20
#define BIGI (1 << 30)

// scratch (no allocs allowed)
__device__ float g_mags[NB * T];
__device__ int   g_idx[NB * KSEL];

// -------- kernel 1: per-(b,t) L2 norm over feature dim --------
// one warp per row; 8 float4 loads per lane, fully coalesced. HBM-bound
// at ~6.9 TB/s (86% of spec) — measured roofline. Untouched.
__global__ void mag_kernel(const float* __restrict__ feat) {
    int warp = (blockIdx.x * blockDim.x + threadIdx.x) >> 5;  // 0 .. 64*2048-1
    int lane = threadIdx.x & 31;
    const float4* row = (const float4*)(feat + (size_t)warp * F);
    float s = 0.f;
#pragma unroll
    for (int i = 0; i < 8; i++) {
        float4 v = row[lane + i * 32];
        s += v.x * v.x + v.y * v.y + v.z * v.z + v.w * v.w;
    }
#pragma unroll
    for (int o = 16; o; o >>= 1) s += __shfl_xor_sync(0xffffffffu, s, o);
    if (lane == 0) g_mags[warp] = sqrtf(s);
}

// -------- kernel 2: top-K + score mean (64 blocks, REDUX-based) ------------
// Values are >= 0, so float bits are monotonic as unsigned. Each round:
// __reduce_max_sync on value bits + __reduce_min_sync on index-among-max
// (2 REDUX ops, ~60cy) instead of a 5-deep shfl tree (~130cy). Exact
// (value desc, index asc) tie-break preserved. Removal sentinel = 0 bits
// (top-20 is always > 0: ~1840 positive candidates per row).
__global__ void __launch_bounds__(256)
topk_kernel(const float* __restrict__ scores,
            const float* __restrict__ mask_abn,
            const float* __restrict__ mask_nor,
            float* __restrict__ out) {
    __shared__ unsigned s_wv[8][21];
    __shared__ int      s_wi[8][21];

    int b = blockIdx.x;
    int tid = threadIdx.x;
    int lane = tid & 31;
    int wid = tid >> 5;

    int batch;
    const float* mask;
    if (b < HB) { batch = HB + b; mask = mask_abn + (size_t)b * T; }
    else        { batch = b - HB; mask = mask_nor + (size_t)(b - HB) * T; }

    const float inv = 1.0f / 0.9f;   // 1/(1-P)
    unsigned u[8];
#pragma unroll
    for (int j = 0; j < 8; j++) {
        int t = wid * 256 + j * 32 + lane;    // warp owns contiguous 256
        float d = (mask[t] > 0.1f) ? inv : 0.0f;
        u[j] = __float_as_uint(g_mags[batch * T + t] * d);  // >= 0 -> monotonic
    }

    // 20 warp-local rounds: local scan + 2 REDUX ops, no block syncs
    for (int k = 0; k < KSEL; k++) {
        unsigned bv = 0; int bi = BIGI;
#pragma unroll
        for (int j = 0; j < 8; j++) {
            if (u[j] > bv) { bv = u[j]; bi = wid * 256 + j * 32 + lane; }
        }
        unsigned mx = __reduce_max_sync(0xffffffffu, bv);
        int cand = (bv == mx) ? bi : BIGI;
        int wix  = (int)__reduce_min_sync(0xffffffffu, (unsigned)cand);
        if (lane == 0) { s_wv[wid][k] = mx; s_wi[wid][k] = wix; }
        int local = wix - wid * 256;          // remove winner from registers
        if ((local & 31) == lane) u[local >> 5] = 0;
    }
    if (lane == 0) { s_wv[wid][20] = 0; s_wi[wid][20] = BIGI; }
    __syncthreads();

    // warp 0: merge 8 descending lists of 20 (lanes 0..7 hold list heads)
    if (wid == 0) {
        int      p  = 0;
        unsigned hv = (lane < 8) ? s_wv[lane][0] : 0;
        int      hi = (lane < 8) ? s_wi[lane][0] : BIGI;
        int my_idx = 0;
        for (int k = 0; k < KSEL; k++) {
            unsigned mx = __reduce_max_sync(0xffffffffu, hv);
            int cand = (hv == mx) ? hi : BIGI;
            int wix  = (int)__reduce_min_sync(0xffffffffu, (unsigned)cand);
            if (lane == k) my_idx = wix;
            if (lane < 8 && hi == wix) {      // advance that list
                p++; hv = s_wv[lane][p]; hi = s_wi[lane][p];
            }
        }
        // indices + score mean (one parallel load pass)
        float sc = 0.f;
        if (lane < KSEL) {
            g_idx[b * KSEL + lane] = my_idx;
            sc = scores[(size_t)batch * T + my_idx];
        }
#pragma unroll
        for (int o = 16; o; o >>= 1) sc += __shfl_xor_sync(0xffffffffu, sc, o);
        if (lane == 0) out[b] = sc / (float)KSEL;   // [0,32)=abn, [32,64)=nor
    }
}

// -------- kernel 3: gather, grid-stride, 4 float4 per thread --------------
#define GTHREADS (320 * 256)

__global__ void __launch_bounds__(256)
gather_kernel(const float* __restrict__ feat,
              float* __restrict__ out) {
    int gid = blockIdx.x * 256 + threadIdx.x;

    const float4* srcp[4];
    int rows[4];
    int cs[4];
#pragma unroll
    for (int i = 0; i < 4; i++) {
        int e   = gid + i * GTHREADS;    // element id
        int row = e >> 8;                // / 256 float4s per row
        int c   = e & 255;
        int orow = row / KSEL;           // 0..63 (abn rows first)
        int k    = row % KSEL;
        int batch = (orow < HB) ? (HB + orow) : (orow - HB);
        int idx = g_idx[orow * KSEL + k];
        srcp[i] = (const float4*)(feat + ((size_t)batch * T + idx) * F) + c;
        rows[i] = row; cs[i] = c;
    }
    // batched loads (MLP=4), then stores
    float4 vbuf[4];
#pragma unroll
    for (int i = 0; i < 4; i++) vbuf[i] = *srcp[i];
    float4* dst = (float4*)(out + 64);
#pragma unroll
    for (int i = 0; i < 4; i++) dst[(size_t)rows[i] * 256 + cs[i]] = vbuf[i];
}

extern "C" void kernel_launch(void* const* d_in, const int* in_sizes, int n_in,
                              void* d_out, int out_size) {
    const float* feat   = (const float*)d_in[0];
    const float* scores = (const float*)d_in[1];
    const float* mabn   = (const float*)d_in[2];
    const float* mnor   = (const float*)d_in[3];
    float* out = (float*)d_out;

    mag_kernel<<<(NB * T) / 8, 256>>>(feat);
    topk_kernel<<<NB, 256>>>(scores, mabn, mnor, out);
    gather_kernel<<<320, 256>>>(feat, out);
}